// round 14
// baseline (speedup 1.0000x reference)
#include <cuda_runtime.h>
#include <cuda_fp16.h>
#include <cstdint>

typedef unsigned long long ull;

#define OBS_DIMV 4096
#define NGVF     4096
#define NA       18
#define TF       36864
#define ROWS     16
#define THREADS  512
#define NWARP    16
#define PAIRS    8
#define OSTRIDE_H2 4100          /* half2 words per pair-row (4096 + 4 pad) */

/* per-warp pipeline: each warp owns its 2-gvf slice stream */
#define NBUF     3
#define NCH      128             /* chunks per warp */
/* warp-chunk slice: idx 32 u32 | W 128 u32 | Q 192 u32 = 352 u32 = 1408 B */
#define CHW32    352
#define CH_BYTES (CHW32 * 4)

/* obs-direct tail slices (fp32) */
#define QO_COLS  256
#define QO_SLICE 4608            /* floats */
#define QO_BYTES (QO_SLICE * 4)
#define NSLICE   (OBS_DIMV / QO_COLS)

/* smem byte offsets */
#define OBS_B    0
#define OBS_BYTES (PAIRS * OSTRIDE_H2 * 4)        /* 131200 */
#define CH_B     OBS_BYTES                        /* 16 warps x 3 bufs x 1408 = 67584 */
#define P_B      (CH_B + NWARP * NBUF * CH_BYTES) /* 198784 */
#define P_BYTES  (NWARP * ROWS * 24 * 4)          /* 24576  */
#define POBS_B   (P_B + P_BYTES)                  /* 223360 */
#define POBS_BYTES (NWARP * NA * 4)               /* 1152   */
#define MBAR_B   (POBS_B + POBS_BYTES)            /* 224512; 48 warp mbarriers + 2 tail */
#define SMEM_BYTES (MBAR_B + 512)                 /* 225024 <= 232448 */

/* ---- repacked weights (rebuilt every launch), per-warp-contiguous ---- */
__device__ __align__(16) uint32_t ChunkPk_g[(size_t)NWARP * NCH * CHW32]; /* 2.88MB */
__device__ __align__(16) float    QobsPk_g[NSLICE * QO_SLICE];

#define N_CHW (NWARP * NCH * CHW32)
#define N_QO  (NSLICE * QO_SLICE)
#define N_TOT (N_CHW + N_QO)

__global__ void repack_kernel(const float* __restrict__ gvfW,
                              const float* __restrict__ qW,
                              const int*   __restrict__ gidx)
{
    int id = blockIdx.x * 256 + threadIdx.x;
    if (id < N_CHW) {
        int wc = id / CHW32;
        int r  = id - wc * CHW32;
        int wi = wc >> 7;           /* global warp 0..15 */
        int c  = wc & 127;          /* chunk */
        int set = wi >> 2, p = wi & 3;
        int gbase = set * 1024 + c * 8 + p * 2;   /* this warp's gvf pair */
        uint32_t val;
        if (r < 32) {
            /* idx int4 tables: gvf gsel at u32 gsel*16 + t*4 + comp */
            int gsel = r >> 4;
            int q = r & 15, t = q >> 2, comp = q & 3;
            int i = (comp < 2) ? (2 * t + comp) : (2 * t + 8 + (comp - 2));
            val = (uint32_t)(gidx[(gbase + gsel) * 16 + i] * 4);
        } else if (r < 160) {
            /* W b-frag: gvf gsel at u32 32 + gsel*64 + lane*2 + half */
            int w2 = r - 32;
            int gsel = w2 >> 6, rem = w2 & 63;
            int lane = rem >> 1, half = rem & 1;
            int h = lane >> 2, t = lane & 3;
            int k0 = half ? (2 * t + 8) : (2 * t);
            float f0 = gvfW[((size_t)(gbase + gsel) * 8 + h) * 16 + k0];
            float f1 = gvfW[((size_t)(gbase + gsel) * 8 + h) * 16 + k0 + 1];
            __half2 hh = __floats2half2_rn(f0, f1);
            val = *reinterpret_cast<uint32_t*>(&hh);
        } else {
            /* Q b-frag: tile at u32 160 + tile*64 + lane*2 + half */
            int qd = r - 160;
            int tile = qd >> 6, rem2 = qd & 63;
            int lane = rem2 >> 1, half = rem2 & 1;
            int n = (lane >> 2) + tile * 8, t = lane & 3;
            int k0 = half ? (2 * t + 8) : (2 * t);
            float q0 = 0.f, q1 = 0.f;
            if (n < 18) {
                int gv = gbase + (k0 >> 3);
                int h0 = k0 & 7;
                q0 = qW[(size_t)n * TF + OBS_DIMV + (size_t)gv * 8 + h0];
                q1 = qW[(size_t)n * TF + OBS_DIMV + (size_t)gv * 8 + h0 + 1];
            }
            __half2 hh = __floats2half2_rn(q0, q1);
            val = *reinterpret_cast<uint32_t*>(&hh);
        }
        ChunkPk_g[id] = val;
    } else if (id < N_TOT) {
        int t = id - N_CHW;
        int s = t / QO_SLICE, r = t - s * QO_SLICE;
        int a2 = r >> 9, u = r & 511, col = u >> 1, sp = u & 1;
        QobsPk_g[t] = qW[(size_t)(2 * a2 + sp) * TF + s * QO_COLS + col];
    }
}

/* ---- mbarrier + bulk-TMA helpers ---- */
__device__ __forceinline__ void mbar_init(uint32_t mbar, uint32_t cnt) {
    asm volatile("mbarrier.init.shared.b64 [%0], %1;" :: "r"(mbar), "r"(cnt) : "memory");
}
__device__ __forceinline__ void mbar_expect_tx(uint32_t mbar, uint32_t bytes) {
    asm volatile("mbarrier.arrive.expect_tx.shared.b64 _, [%0], %1;"
                 :: "r"(mbar), "r"(bytes) : "memory");
}
__device__ __forceinline__ void bulk_g2s(uint32_t dst, const void* src,
                                         uint32_t bytes, uint32_t mbar) {
    asm volatile("cp.async.bulk.shared::cta.global.mbarrier::complete_tx::bytes "
                 "[%0], [%1], %2, [%3];"
                 :: "r"(dst), "l"(src), "r"(bytes), "r"(mbar) : "memory");
}
__device__ __forceinline__ void mbar_wait(uint32_t mbar, uint32_t parity) {
    asm volatile(
        "{\n\t"
        ".reg .pred P;\n"
        "LW_%=:\n\t"
        "mbarrier.try_wait.parity.acquire.cta.shared::cta.b64 P, [%0], %1, 0x989680;\n\t"
        "@P bra.uni LD_%=;\n\t"
        "bra.uni LW_%=;\n"
        "LD_%=:\n\t"
        "}"
        :: "r"(mbar), "r"(parity) : "memory");
}
__device__ __forceinline__ void fence_async() {
    asm volatile("fence.proxy.async.shared::cta;" ::: "memory");
}

/* ---- mma + cvt helpers ---- */
__device__ __forceinline__ void mma16816(float& d0, float& d1, float& d2, float& d3,
    uint32_t a0, uint32_t a1, uint32_t a2, uint32_t a3,
    uint32_t b0, uint32_t b1,
    float c0, float c1, float c2, float c3)
{
    asm volatile("mma.sync.aligned.m16n8k16.row.col.f32.f16.f16.f32 "
        "{%0,%1,%2,%3},{%4,%5,%6,%7},{%8,%9},{%10,%11,%12,%13};"
        : "=f"(d0), "=f"(d1), "=f"(d2), "=f"(d3)
        : "r"(a0), "r"(a1), "r"(a2), "r"(a3), "r"(b0), "r"(b1),
          "f"(c0), "f"(c1), "f"(c2), "f"(c3));
}
__device__ __forceinline__ uint32_t cvt_f16x2(float hi, float lo) {
    uint32_t r; asm("cvt.rn.f16x2.f32 %0, %1, %2;" : "=r"(r) : "f"(hi), "f"(lo)); return r;
}
__device__ __forceinline__ uint32_t hmax2_z(uint32_t v) {
    uint32_t r; asm("max.f16x2 %0, %1, %2;" : "=r"(r) : "r"(v), "r"(0u)); return r;
}

/* ---- f32x2 helpers (tail only) ---- */
__device__ __forceinline__ ull pack2(float a, float b) {
    ull r; asm("mov.b64 %0,{%1,%2};" : "=l"(r) : "f"(a), "f"(b)); return r;
}
__device__ __forceinline__ float2 unpack2(ull v) {
    float2 f; asm("mov.b64 {%0,%1},%2;" : "=f"(f.x), "=f"(f.y) : "l"(v)); return f;
}
__device__ __forceinline__ void ffma2(ull& d, ull a, ull b) {
    asm("fma.rn.f32x2 %0,%1,%2,%0;" : "+l"(d) : "l"(a), "l"(b));
}
__device__ __forceinline__ ull addf2(ull a, ull b) {
    ull r; asm("add.rn.f32x2 %0,%1,%2;" : "=l"(r) : "l"(a), "l"(b)); return r;
}

extern __shared__ float smf[];

__global__ void __launch_bounds__(THREADS, 1)
nibbler_main(const float* __restrict__ obs, float* __restrict__ out)
{
    const int tid  = threadIdx.x;
    const int w    = tid >> 5;
    const int lane = tid & 31;
    const int g    = lane >> 2;
    const int t    = lane & 3;
    const int r0   = blockIdx.x * ROWS;

    char* smb = (char*)smf;
    uint32_t sbase = (uint32_t)__cvta_generic_to_shared(smf);
    const uint32_t MBASE = sbase + MBAR_B;
    const uint32_t MT[2] = { MBASE + 384u, MBASE + 392u };

    if (tid == 0) {
        #pragma unroll
        for (int i = 0; i < NWARP * NBUF; ++i) mbar_init(MBASE + (uint32_t)i * 8u, 1);
        mbar_init(MT[0], 1);
        mbar_init(MT[1], 1);
    }
    __syncthreads();

    /* per-warp pipeline state */
    const uint32_t MW  = MBASE + (uint32_t)(w * NBUF) * 8u;
    const uint32_t CWB = sbase + (uint32_t)(CH_B + w * NBUF * CH_BYTES);
    const char*    CWP = smb + CH_B + w * NBUF * CH_BYTES;
    const uint32_t* SRCW = ChunkPk_g + (size_t)w * NCH * CHW32;

    if (lane == 0) {
        #pragma unroll
        for (int b = 0; b < NBUF; ++b) {
            mbar_expect_tx(MW + (uint32_t)b * 8u, CH_BYTES);
            bulk_g2s(CWB + (uint32_t)b * CH_BYTES, SRCW + (size_t)b * CHW32,
                     CH_BYTES, MW + (uint32_t)b * 8u);
        }
    }

    /* stage obs as half2 row-pairs (row pp low, row pp+8 high) */
    {
        __half2* sObs = reinterpret_cast<__half2*>(smf);
        #pragma unroll 4
        for (int id = tid; id < PAIRS * (OBS_DIMV / 4); id += THREADS) {
            int pp = id >> 10, j = id & 1023;
            float4 va = *(const float4*)(obs + (size_t)(r0 + pp    ) * OBS_DIMV + j * 4);
            float4 vb = *(const float4*)(obs + (size_t)(r0 + pp + 8) * OBS_DIMV + j * 4);
            __half2 h0 = __floats2half2_rn(va.x, vb.x);
            __half2 h1 = __floats2half2_rn(va.y, vb.y);
            __half2 h2 = __floats2half2_rn(va.z, vb.z);
            __half2 h3 = __floats2half2_rn(va.w, vb.w);
            uint4 pk;
            pk.x = *reinterpret_cast<uint32_t*>(&h0);
            pk.y = *reinterpret_cast<uint32_t*>(&h1);
            pk.z = *reinterpret_cast<uint32_t*>(&h2);
            pk.w = *reinterpret_cast<uint32_t*>(&h3);
            *(uint4*)(sObs + pp * OSTRIDE_H2 + j * 4) = pk;
        }
    }
    __syncthreads();

    const char* obp = smb + g * (OSTRIDE_H2 * 4);

    float D00 = 0.f, D01 = 0.f, D02 = 0.f, D03 = 0.f;
    float D10 = 0.f, D11 = 0.f, D12 = 0.f, D13 = 0.f;
    float D20 = 0.f, D21 = 0.f, D22 = 0.f, D23 = 0.f;

/* per-half body: gathers + Q loads for chunk CC (frags IVA/WFA already in
   regs), prefetch idx+W of CC+1 into IVB/WFB, warp-local release + restage,
   then the mma chain. NO cross-warp synchronization. */
#define HALF_BODY(CC, IVA0, IVA1, WFA0, WFA1, IVB0, IVB1, WFB0, WFB1)            \
    {                                                                            \
        const int b_ = (CC) % NBUF;                                              \
        const char* chb_ = CWP + b_ * CH_BYTES;                                  \
        uint32_t wa = *(const uint32_t*)(obp + IVA0.x);                          \
        uint32_t wb = *(const uint32_t*)(obp + IVA0.y);                          \
        uint32_t wc = *(const uint32_t*)(obp + IVA0.z);                          \
        uint32_t wd = *(const uint32_t*)(obp + IVA0.w);                          \
        uint32_t xa = *(const uint32_t*)(obp + IVA1.x);                          \
        uint32_t xb = *(const uint32_t*)(obp + IVA1.y);                          \
        uint32_t xc = *(const uint32_t*)(obp + IVA1.z);                          \
        uint32_t xd = *(const uint32_t*)(obp + IVA1.w);                          \
        uint2 Qf0 = *(const uint2*)(chb_ + 640 + lane * 8);                      \
        uint2 Qf1 = *(const uint2*)(chb_ + 896 + lane * 8);                      \
        uint2 Qf2 = *(const uint2*)(chb_ + 1152 + lane * 8);                     \
        if ((CC) + 1 < NCH) {                                                    \
            const int bn_ = ((CC) + 1) % NBUF;                                   \
            mbar_wait(MW + (uint32_t)bn_ * 8u, (((CC) + 1) / NBUF) & 1);         \
            const char* chn_ = CWP + bn_ * CH_BYTES;                             \
            IVB0 = ((const int4*)chn_)[t];                                       \
            IVB1 = ((const int4*)(chn_ + 64))[t];                                \
            WFB0 = *(const uint2*)(chn_ + 128 + lane * 8);                       \
            WFB1 = *(const uint2*)(chn_ + 384 + lane * 8);                       \
        }                                                                        \
        __syncwarp();    /* all 32 lanes have buffer b_ contents in regs */      \
        if (lane == 0 && (CC) + NBUF < NCH) {                                    \
            fence_async();                                                       \
            mbar_expect_tx(MW + (uint32_t)b_ * 8u, CH_BYTES);                    \
            bulk_g2s(CWB + (uint32_t)b_ * CH_BYTES,                              \
                     SRCW + (size_t)((CC) + NBUF) * CHW32, CH_BYTES,             \
                     MW + (uint32_t)b_ * 8u);                                    \
        }                                                                        \
        uint32_t A00 = __byte_perm(wa, wb, 0x5410);                              \
        uint32_t A01 = __byte_perm(wa, wb, 0x7632);                              \
        uint32_t A02 = __byte_perm(wc, wd, 0x5410);                              \
        uint32_t A03 = __byte_perm(wc, wd, 0x7632);                              \
        uint32_t A10 = __byte_perm(xa, xb, 0x5410);                              \
        uint32_t A11 = __byte_perm(xa, xb, 0x7632);                              \
        uint32_t A12 = __byte_perm(xc, xd, 0x5410);                              \
        uint32_t A13 = __byte_perm(xc, xd, 0x7632);                              \
        float h00, h01, h02, h03, h10, h11, h12, h13;                            \
        mma16816(h00, h01, h02, h03, A00, A01, A02, A03, WFA0.x, WFA0.y,         \
                 0.f, 0.f, 0.f, 0.f);                                            \
        mma16816(h10, h11, h12, h13, A10, A11, A12, A13, WFA1.x, WFA1.y,         \
                 0.f, 0.f, 0.f, 0.f);                                            \
        uint32_t qa0 = hmax2_z(cvt_f16x2(h01, h00));                             \
        uint32_t qa1 = hmax2_z(cvt_f16x2(h03, h02));                             \
        uint32_t qa2 = hmax2_z(cvt_f16x2(h11, h10));                             \
        uint32_t qa3 = hmax2_z(cvt_f16x2(h13, h12));                             \
        mma16816(D00, D01, D02, D03, qa0, qa1, qa2, qa3, Qf0.x, Qf0.y,           \
                 D00, D01, D02, D03);                                            \
        mma16816(D10, D11, D12, D13, qa0, qa1, qa2, qa3, Qf1.x, Qf1.y,           \
                 D10, D11, D12, D13);                                            \
        mma16816(D20, D21, D22, D23, qa0, qa1, qa2, qa3, Qf2.x, Qf2.y,           \
                 D20, D21, D22, D23);                                            \
    }

    /* preamble: wait buf 0, load idx+W frags of chunk 0 */
    int4 ivA0, ivA1, ivB0, ivB1;
    uint2 WfA0, WfA1, WfB0, WfB1;
    {
        mbar_wait(MW, 0);
        ivA0 = ((const int4*)CWP)[t];
        ivA1 = ((const int4*)(CWP + 64))[t];
        WfA0 = *(const uint2*)(CWP + 128 + lane * 8);
        WfA1 = *(const uint2*)(CWP + 384 + lane * 8);
    }

    #pragma unroll 1
    for (int c = 0; c < NCH; c += 2) {
        HALF_BODY(c,     ivA0, ivA1, WfA0, WfA1, ivB0, ivB1, WfB0, WfB1)
        HALF_BODY(c + 1, ivB0, ivB1, WfB0, WfB1, ivA0, ivA1, WfA0, WfA1)
    }
#undef HALF_BODY

    /* store per-warp D partials */
    {
        float* P = (float*)(smb + P_B) + w * (ROWS * 24);
        P[(g    ) * 24 + 2 * t     + 0] = D00;
        P[(g    ) * 24 + 2 * t + 1 + 0] = D01;
        P[(g + 8) * 24 + 2 * t     + 0] = D02;
        P[(g + 8) * 24 + 2 * t + 1 + 0] = D03;
        P[(g    ) * 24 + 2 * t     + 8] = D10;
        P[(g    ) * 24 + 2 * t + 1 + 8] = D11;
        P[(g + 8) * 24 + 2 * t     + 8] = D12;
        P[(g + 8) * 24 + 2 * t + 1 + 8] = D13;
        P[(g    ) * 24 + 2 * t     + 16] = D20;
        P[(g    ) * 24 + 2 * t + 1 + 16] = D21;
        P[(g + 8) * 24 + 2 * t     + 16] = D22;
        P[(g + 8) * 24 + 2 * t + 1 + 16] = D23;
    }
    __syncthreads();   /* chunk buffers now reusable for tail */

    /* ---- obs-direct Q tail: TMA-staged fp32 slices ---- */
    {
        uint32_t TB0 = sbase + (uint32_t)CH_B;
        if (tid == 0) {
            mbar_expect_tx(MT[0], QO_BYTES);
            bulk_g2s(TB0, QobsPk_g, QO_BYTES, MT[0]);
            mbar_expect_tx(MT[1], QO_BYTES);
            bulk_g2s(TB0 + QO_BYTES, QobsPk_g + QO_SLICE, QO_BYTES, MT[1]);
        }

        ull oacc[9];
        #pragma unroll
        for (int a2 = 0; a2 < 9; ++a2) oacc[a2] = 0ull;
        const float* orow = obs + (size_t)(r0 + w) * OBS_DIMV;

        #pragma unroll 1
        for (int s = 0; s < NSLICE; ++s) {
            mbar_wait(MT[s & 1], (s >> 1) & 1);
            __syncthreads();
            if (tid == 0 && s >= 1 && s + 1 < NSLICE) {
                int b2 = (s + 1) & 1;
                fence_async();
                mbar_expect_tx(MT[b2], QO_BYTES);
                bulk_g2s(TB0 + (uint32_t)b2 * QO_BYTES,
                         QobsPk_g + (size_t)(s + 1) * QO_SLICE, QO_BYTES, MT[b2]);
            }
            const float* qs = (const float*)(smb + CH_B) + (s & 1) * QO_SLICE;
            #pragma unroll
            for (int jj = 0; jj < 4; ++jj) {
                int jloc = jj * 64 + lane * 2;
                float2 ov = *(const float2*)(orow + s * QO_COLS + jloc);
                ull oA = pack2(ov.x, ov.x);
                ull oB = pack2(ov.y, ov.y);
                #pragma unroll
                for (int a2 = 0; a2 < 9; ++a2) {
                    ulonglong2 qv = *(const ulonglong2*)(qs + a2 * (QO_COLS * 2) + jloc * 2);
                    ffma2(oacc[a2], qv.x, oA);
                    ffma2(oacc[a2], qv.y, oB);
                }
            }
        }

        #pragma unroll
        for (int a2 = 0; a2 < 9; ++a2) {
            #pragma unroll
            for (int off = 16; off >= 1; off >>= 1) {
                ull o = __shfl_xor_sync(0xffffffffu, oacc[a2], off);
                oacc[a2] = addf2(oacc[a2], o);
            }
        }
        if (lane == 0) {
            float* Po = (float*)(smb + POBS_B) + w * NA;
            #pragma unroll
            for (int a2 = 0; a2 < 9; ++a2) {
                float2 v = unpack2(oacc[a2]);
                Po[2 * a2]     = v.x;
                Po[2 * a2 + 1] = v.y;
            }
        }
    }
    __syncthreads();

    /* final: 288 threads sum 16 warp partials + obs partial */
    if (tid < ROWS * NA) {
        int rr = tid / NA;
        int a  = tid - rr * NA;
        const float* P = (const float*)(smb + P_B);
        float s = 0.f;
        #pragma unroll
        for (int pw = 0; pw < NWARP; ++pw)
            s += P[pw * (ROWS * 24) + rr * 24 + a];
        s += ((const float*)(smb + POBS_B))[rr * NA + a];
        out[(size_t)(r0 + rr) * NA + a] = s;
    }
}

extern "C" void kernel_launch(void* const* d_in, const int* in_sizes, int n_in,
                              void* d_out, int out_size)
{
    const float* obs  = (const float*)d_in[0];
    const float* gvfW = (const float*)d_in[1];
    const float* qW   = (const float*)d_in[2];
    const int*   gidx = (const int*)d_in[3];
    float* out = (float*)d_out;

    repack_kernel<<<(N_TOT + 255) / 256, 256>>>(gvfW, qW, gidx);

    cudaFuncSetAttribute(nibbler_main,
                         cudaFuncAttributeMaxDynamicSharedMemorySize, SMEM_BYTES);
    nibbler_main<<<2048 / ROWS, THREADS, SMEM_BYTES>>>(obs, out);
}

// round 16
// speedup vs baseline: 1.4396x; 1.4396x over previous
#include <cuda_runtime.h>
#include <cuda_fp16.h>
#include <cstdint>

typedef unsigned long long ull;

#define OBS_DIMV 4096
#define NGVF     4096
#define NA       18
#define TF       36864
#define ROWS     16
#define THREADS  512
#define NWARP    16
#define PAIRS    8
#define OSTRIDE_H2 4100          /* half2 words per pair-row (4096 + 4 pad) */

/* 8-gvf chunks, 4 warp-sets (4 warps each), 3 buffers per set (R13-proven) */
#define NSET     4
#define NBUF     3
#define NCH      128             /* chunks per set */
/* chunk layout (u32 words): idx 128 | W 512 | Q 768  = 1408 words = 5632 B */
#define CHW32    1408
#define CH_BYTES (CHW32 * 4)
#define W_RELB   512
#define Q_RELB   2560

/* smem byte offsets */
#define OBS_B    0
#define OBS_BYTES (PAIRS * OSTRIDE_H2 * 4)        /* 131200 */
#define CH_B     OBS_BYTES                        /* 12 bufs x 5632 = 67584 */
#define P_B      (CH_B + NSET * NBUF * CH_BYTES)  /* 198784 */
#define P_BYTES  (NWARP * ROWS * 24 * 4)          /* 24576  */
#define MBAR_B   (P_B + P_BYTES)                  /* 223360; 12 set mbarriers */
#define SMEM_BYTES (MBAR_B + 128)                 /* 223488 <= 232448 */

/* ---- repacked weights (rebuilt every launch) ---- */
__device__ __align__(16) uint32_t ChunkPk_g[(size_t)NSET * NCH * CHW32]; /* 2.88MB */
/* obs-direct Q b-frag table: [w][step j<16][tile<3][lane][half] u32 */
__device__ __align__(16) uint32_t QoF_g[NWARP * 16 * 3 * 64];            /* 196.6KB */

#define N_CHW (NSET * NCH * CHW32)       /* 720896 */
#define N_QOF (NWARP * 16 * 3 * 64)      /* 49152  */
#define N_TOT (N_CHW + N_QOF)

__global__ void repack_kernel(const float* __restrict__ gvfW,
                              const float* __restrict__ qW,
                              const int*   __restrict__ gidx)
{
    int id = blockIdx.x * 256 + threadIdx.x;
    if (id < N_CHW) {
        int sc = id / CHW32;
        int r  = id - sc * CHW32;
        int gbase = (sc >> 7) * 1024 + (sc & 127) * 8;
        uint32_t val;
        if (r < 128) {
            int g = r >> 4, t = (r >> 2) & 3, comp = r & 3;
            int i = (comp < 2) ? (2 * t + comp) : (2 * t + 8 + (comp - 2));
            val = (uint32_t)(gidx[(gbase + g) * 16 + i] * 4);
        } else if (r < 640) {
            int w2 = r - 128;
            int g = w2 >> 6, rem = w2 & 63;
            int lane = rem >> 1, half = rem & 1;
            int h = lane >> 2, t = lane & 3;
            int k0 = half ? (2 * t + 8) : (2 * t);
            float f0 = gvfW[((size_t)(gbase + g) * 8 + h) * 16 + k0];
            float f1 = gvfW[((size_t)(gbase + g) * 8 + h) * 16 + k0 + 1];
            __half2 hh = __floats2half2_rn(f0, f1);
            val = *reinterpret_cast<uint32_t*>(&hh);
        } else {
            int qd = r - 640;
            int p = qd / 192, rem = qd - p * 192;
            int tile = rem >> 6, rem2 = rem & 63;
            int lane = rem2 >> 1, half = rem2 & 1;
            int n = (lane >> 2) + tile * 8, t = lane & 3;
            int k0 = half ? (2 * t + 8) : (2 * t);
            float q0 = 0.f, q1 = 0.f;
            if (n < 18) {
                int gv = gbase + p * 2 + (k0 >> 3);
                int h0 = k0 & 7;
                q0 = qW[(size_t)n * TF + OBS_DIMV + (size_t)gv * 8 + h0];
                q1 = qW[(size_t)n * TF + OBS_DIMV + (size_t)gv * 8 + h0 + 1];
            }
            __half2 hh = __floats2half2_rn(q0, q1);
            val = *reinterpret_cast<uint32_t*>(&hh);
        }
        ChunkPk_g[id] = val;
    } else if (id < N_TOT) {
        /* obs-direct Q b-frags (fp16): u = ((w*16+j)*3+tile)*64 + lane*2 + half */
        int u = id - N_CHW;
        int w  = u / 3072;
        int r1 = u - w * 3072;
        int j  = r1 / 192;
        int r2 = r1 - j * 192;
        int tile = r2 >> 6, r3 = r2 & 63;
        int lane = r3 >> 1, half = r3 & 1;
        int n = tile * 8 + (lane >> 2), t = lane & 3;
        int k0 = half ? (2 * t + 8) : (2 * t);
        int col = w * 256 + j * 16 + k0;
        float q0 = 0.f, q1 = 0.f;
        if (n < 18) {
            q0 = qW[(size_t)n * TF + col];
            q1 = qW[(size_t)n * TF + col + 1];
        }
        __half2 hh = __floats2half2_rn(q0, q1);
        QoF_g[u] = *reinterpret_cast<uint32_t*>(&hh);
    }
}

/* ---- mbarrier + bulk-TMA helpers ---- */
__device__ __forceinline__ void mbar_init(uint32_t mbar, uint32_t cnt) {
    asm volatile("mbarrier.init.shared.b64 [%0], %1;" :: "r"(mbar), "r"(cnt) : "memory");
}
__device__ __forceinline__ void mbar_expect_tx(uint32_t mbar, uint32_t bytes) {
    asm volatile("mbarrier.arrive.expect_tx.shared.b64 _, [%0], %1;"
                 :: "r"(mbar), "r"(bytes) : "memory");
}
__device__ __forceinline__ void bulk_g2s(uint32_t dst, const void* src,
                                         uint32_t bytes, uint32_t mbar) {
    asm volatile("cp.async.bulk.shared::cta.global.mbarrier::complete_tx::bytes "
                 "[%0], [%1], %2, [%3];"
                 :: "r"(dst), "l"(src), "r"(bytes), "r"(mbar) : "memory");
}
__device__ __forceinline__ void mbar_wait(uint32_t mbar, uint32_t parity) {
    asm volatile(
        "{\n\t"
        ".reg .pred P;\n"
        "LW_%=:\n\t"
        "mbarrier.try_wait.parity.acquire.cta.shared::cta.b64 P, [%0], %1, 0x989680;\n\t"
        "@P bra.uni LD_%=;\n\t"
        "bra.uni LW_%=;\n"
        "LD_%=:\n\t"
        "}"
        :: "r"(mbar), "r"(parity) : "memory");
}
__device__ __forceinline__ void set_bar(int id) {
    asm volatile("bar.sync %0, 128;" :: "r"(id) : "memory");
}
__device__ __forceinline__ void fence_async() {
    asm volatile("fence.proxy.async.shared::cta;" ::: "memory");
}

/* ---- mma + cvt helpers ---- */
__device__ __forceinline__ void mma16816(float& d0, float& d1, float& d2, float& d3,
    uint32_t a0, uint32_t a1, uint32_t a2, uint32_t a3,
    uint32_t b0, uint32_t b1,
    float c0, float c1, float c2, float c3)
{
    asm volatile("mma.sync.aligned.m16n8k16.row.col.f32.f16.f16.f32 "
        "{%0,%1,%2,%3},{%4,%5,%6,%7},{%8,%9},{%10,%11,%12,%13};"
        : "=f"(d0), "=f"(d1), "=f"(d2), "=f"(d3)
        : "r"(a0), "r"(a1), "r"(a2), "r"(a3), "r"(b0), "r"(b1),
          "f"(c0), "f"(c1), "f"(c2), "f"(c3));
}
__device__ __forceinline__ uint32_t cvt_f16x2(float hi, float lo) {
    uint32_t r; asm("cvt.rn.f16x2.f32 %0, %1, %2;" : "=r"(r) : "f"(hi), "f"(lo)); return r;
}
__device__ __forceinline__ uint32_t hmax2_z(uint32_t v) {
    uint32_t r; asm("max.f16x2 %0, %1, %2;" : "=r"(r) : "r"(v), "r"(0u)); return r;
}

extern __shared__ float smf[];

__global__ void __launch_bounds__(THREADS, 1)
nibbler_main(const float* __restrict__ obs, float* __restrict__ out)
{
    const int tid  = threadIdx.x;
    const int w    = tid >> 5;
    const int lane = tid & 31;
    const int set  = w >> 2;
    const int p    = w & 3;
    const int g    = lane >> 2;
    const int t    = lane & 3;
    const int r0   = blockIdx.x * ROWS;

    char* smb = (char*)smf;
    uint32_t sbase = (uint32_t)__cvta_generic_to_shared(smf);
    const uint32_t MBASE = sbase + MBAR_B;

    if (tid == 0) {
        #pragma unroll
        for (int i = 0; i < NSET * NBUF; ++i) mbar_init(MBASE + (uint32_t)i * 8u, 1);
    }
    __syncthreads();

    const bool producer = (tid == set * 128);
    const uint32_t MBf = MBASE + (uint32_t)(set * NBUF) * 8u;
    const uint32_t CHB = sbase + (uint32_t)(CH_B + set * NBUF * CH_BYTES);
    const uint32_t* SRC = ChunkPk_g + (size_t)set * NCH * CHW32;

    if (producer) {
        #pragma unroll
        for (int b = 0; b < NBUF; ++b) {
            mbar_expect_tx(MBf + (uint32_t)b * 8u, CH_BYTES);
            bulk_g2s(CHB + (uint32_t)b * CH_BYTES, SRC + (size_t)b * CHW32,
                     CH_BYTES, MBf + (uint32_t)b * 8u);
        }
    }

    /* stage obs as half2 row-pairs (row pp low, row pp+8 high) */
    {
        __half2* sObs = reinterpret_cast<__half2*>(smf);
        #pragma unroll 4
        for (int id = tid; id < PAIRS * (OBS_DIMV / 4); id += THREADS) {
            int pp = id >> 10, j = id & 1023;
            float4 va = *(const float4*)(obs + (size_t)(r0 + pp    ) * OBS_DIMV + j * 4);
            float4 vb = *(const float4*)(obs + (size_t)(r0 + pp + 8) * OBS_DIMV + j * 4);
            __half2 h0 = __floats2half2_rn(va.x, vb.x);
            __half2 h1 = __floats2half2_rn(va.y, vb.y);
            __half2 h2 = __floats2half2_rn(va.z, vb.z);
            __half2 h3 = __floats2half2_rn(va.w, vb.w);
            uint4 pk;
            pk.x = *reinterpret_cast<uint32_t*>(&h0);
            pk.y = *reinterpret_cast<uint32_t*>(&h1);
            pk.z = *reinterpret_cast<uint32_t*>(&h2);
            pk.w = *reinterpret_cast<uint32_t*>(&h3);
            *(uint4*)(sObs + pp * OSTRIDE_H2 + j * 4) = pk;
        }
    }
    __syncthreads();

    const char* obp = smb + g * (OSTRIDE_H2 * 4);

    float D00 = 0.f, D01 = 0.f, D02 = 0.f, D03 = 0.f;
    float D10 = 0.f, D11 = 0.f, D12 = 0.f, D13 = 0.f;
    float D20 = 0.f, D21 = 0.f, D22 = 0.f, D23 = 0.f;

/* per-half body (R13-proven): gathers + Q loads for chunk CC, prefetch idx+W
   of CC+1, set-barrier release, producer restage, mma chain */
#define HALF_BODY(CC, IVA0, IVA1, WFA0, WFA1, IVB0, IVB1, WFB0, WFB1)            \
    {                                                                            \
        const int b_   = (CC) % NBUF;                                            \
        const char* chb_ = smb + CH_B + (set * NBUF + b_) * CH_BYTES;            \
        uint32_t wa = *(const uint32_t*)(obp + IVA0.x);                          \
        uint32_t wb = *(const uint32_t*)(obp + IVA0.y);                          \
        uint32_t wc = *(const uint32_t*)(obp + IVA0.z);                          \
        uint32_t wd = *(const uint32_t*)(obp + IVA0.w);                          \
        uint32_t xa = *(const uint32_t*)(obp + IVA1.x);                          \
        uint32_t xb = *(const uint32_t*)(obp + IVA1.y);                          \
        uint32_t xc = *(const uint32_t*)(obp + IVA1.z);                          \
        uint32_t xd = *(const uint32_t*)(obp + IVA1.w);                          \
        const char* qb_ = chb_ + Q_RELB + p * 768;                               \
        uint2 Qf0 = *(const uint2*)(qb_ + lane * 8);                             \
        uint2 Qf1 = *(const uint2*)(qb_ + 256 + lane * 8);                       \
        uint2 Qf2 = *(const uint2*)(qb_ + 512 + lane * 8);                       \
        if ((CC) + 1 < NCH) {                                                    \
            const int bn_ = ((CC) + 1) % NBUF;                                   \
            mbar_wait(MBf + (uint32_t)bn_ * 8u, (((CC) + 1) / NBUF) & 1);        \
            const char* chn_ = smb + CH_B + (set * NBUF + bn_) * CH_BYTES;       \
            IVB0 = ((const int4*)chn_)[(2 * p) * 4 + t];                         \
            IVB1 = ((const int4*)chn_)[(2 * p + 1) * 4 + t];                     \
            WFB0 = *(const uint2*)(chn_ + W_RELB + (2 * p) * 256 + lane * 8);    \
            WFB1 = *(const uint2*)(chn_ + W_RELB + (2 * p + 1) * 256 + lane * 8);\
        }                                                                        \
        set_bar(1 + set);                                                        \
        if (producer && (CC) + NBUF < NCH) {                                     \
            fence_async();                                                       \
            mbar_expect_tx(MBf + (uint32_t)b_ * 8u, CH_BYTES);                   \
            bulk_g2s(CHB + (uint32_t)b_ * CH_BYTES,                              \
                     SRC + (size_t)((CC) + NBUF) * CHW32, CH_BYTES,              \
                     MBf + (uint32_t)b_ * 8u);                                   \
        }                                                                        \
        uint32_t A00 = __byte_perm(wa, wb, 0x5410);                              \
        uint32_t A01 = __byte_perm(wa, wb, 0x7632);                              \
        uint32_t A02 = __byte_perm(wc, wd, 0x5410);                              \
        uint32_t A03 = __byte_perm(wc, wd, 0x7632);                              \
        uint32_t A10 = __byte_perm(xa, xb, 0x5410);                              \
        uint32_t A11 = __byte_perm(xa, xb, 0x7632);                              \
        uint32_t A12 = __byte_perm(xc, xd, 0x5410);                              \
        uint32_t A13 = __byte_perm(xc, xd, 0x7632);                              \
        float h00, h01, h02, h03, h10, h11, h12, h13;                            \
        mma16816(h00, h01, h02, h03, A00, A01, A02, A03, WFA0.x, WFA0.y,         \
                 0.f, 0.f, 0.f, 0.f);                                            \
        mma16816(h10, h11, h12, h13, A10, A11, A12, A13, WFA1.x, WFA1.y,         \
                 0.f, 0.f, 0.f, 0.f);                                            \
        uint32_t qa0 = hmax2_z(cvt_f16x2(h01, h00));                             \
        uint32_t qa1 = hmax2_z(cvt_f16x2(h03, h02));                             \
        uint32_t qa2 = hmax2_z(cvt_f16x2(h11, h10));                             \
        uint32_t qa3 = hmax2_z(cvt_f16x2(h13, h12));                             \
        mma16816(D00, D01, D02, D03, qa0, qa1, qa2, qa3, Qf0.x, Qf0.y,           \
                 D00, D01, D02, D03);                                            \
        mma16816(D10, D11, D12, D13, qa0, qa1, qa2, qa3, Qf1.x, Qf1.y,           \
                 D10, D11, D12, D13);                                            \
        mma16816(D20, D21, D22, D23, qa0, qa1, qa2, qa3, Qf2.x, Qf2.y,           \
                 D20, D21, D22, D23);                                            \
    }

    /* preamble: load idx+W frags of chunk 0 */
    int4 ivA0, ivA1, ivB0, ivB1;
    uint2 WfA0, WfA1, WfB0, WfB1;
    {
        mbar_wait(MBf, 0);
        const char* ch0 = smb + CH_B + (set * NBUF) * CH_BYTES;
        ivA0 = ((const int4*)ch0)[(2 * p) * 4 + t];
        ivA1 = ((const int4*)ch0)[(2 * p + 1) * 4 + t];
        WfA0 = *(const uint2*)(ch0 + W_RELB + (2 * p) * 256 + lane * 8);
        WfA1 = *(const uint2*)(ch0 + W_RELB + (2 * p + 1) * 256 + lane * 8);
    }

    #pragma unroll 1
    for (int c = 0; c < NCH; c += 2) {
        HALF_BODY(c,     ivA0, ivA1, WfA0, WfA1, ivB0, ivB1, WfB0, WfB1)
        HALF_BODY(c + 1, ivB0, ivB1, WfB0, WfB1, ivA0, ivA1, WfA0, WfA1)
    }
#undef HALF_BODY

    /* ---- obs-direct Q part: 16 mma k-steps per warp, A from smem obs,
       B-frags via direct LDG (L2-resident), same D accumulators ---- */
    {
        const uint2* Qo = (const uint2*)QoF_g + (size_t)w * 1536;
        const int kw = w * 256;
        #pragma unroll 2
        for (int j = 0; j < 16; ++j) {
            int kb = kw + j * 16;
            ull v01 = *(const ull*)(obp + (kb + 2 * t) * 4);
            ull v89 = *(const ull*)(obp + (kb + 2 * t + 8) * 4);
            uint2 q0 = Qo[(j * 3 + 0) * 32 + lane];
            uint2 q1 = Qo[(j * 3 + 1) * 32 + lane];
            uint2 q2 = Qo[(j * 3 + 2) * 32 + lane];
            uint32_t c0 = (uint32_t)v01, c1 = (uint32_t)(v01 >> 32);
            uint32_t c2 = (uint32_t)v89, c3 = (uint32_t)(v89 >> 32);
            uint32_t A0 = __byte_perm(c0, c1, 0x5410);
            uint32_t A1 = __byte_perm(c0, c1, 0x7632);
            uint32_t A2 = __byte_perm(c2, c3, 0x5410);
            uint32_t A3 = __byte_perm(c2, c3, 0x7632);
            mma16816(D00, D01, D02, D03, A0, A1, A2, A3, q0.x, q0.y,
                     D00, D01, D02, D03);
            mma16816(D10, D11, D12, D13, A0, A1, A2, A3, q1.x, q1.y,
                     D10, D11, D12, D13);
            mma16816(D20, D21, D22, D23, A0, A1, A2, A3, q2.x, q2.y,
                     D20, D21, D22, D23);
        }
    }

    /* store per-warp D partials: P[w][r][a] */
    {
        float* P = (float*)(smb + P_B) + w * (ROWS * 24);
        P[(g    ) * 24 + 2 * t     + 0] = D00;
        P[(g    ) * 24 + 2 * t + 1 + 0] = D01;
        P[(g + 8) * 24 + 2 * t     + 0] = D02;
        P[(g + 8) * 24 + 2 * t + 1 + 0] = D03;
        P[(g    ) * 24 + 2 * t     + 8] = D10;
        P[(g    ) * 24 + 2 * t + 1 + 8] = D11;
        P[(g + 8) * 24 + 2 * t     + 8] = D12;
        P[(g + 8) * 24 + 2 * t + 1 + 8] = D13;
        P[(g    ) * 24 + 2 * t     + 16] = D20;
        P[(g    ) * 24 + 2 * t + 1 + 16] = D21;
        P[(g + 8) * 24 + 2 * t     + 16] = D22;
        P[(g + 8) * 24 + 2 * t + 1 + 16] = D23;
    }
    __syncthreads();

    /* final: 288 threads sum 16 warp partials */
    if (tid < ROWS * NA) {
        int rr = tid / NA;
        int a  = tid - rr * NA;
        const float* P = (const float*)(smb + P_B);
        float s = 0.f;
        #pragma unroll
        for (int pw = 0; pw < NWARP; ++pw)
            s += P[pw * (ROWS * 24) + rr * 24 + a];
        out[(size_t)(r0 + rr) * NA + a] = s;
    }
}

extern "C" void kernel_launch(void* const* d_in, const int* in_sizes, int n_in,
                              void* d_out, int out_size)
{
    const float* obs  = (const float*)d_in[0];
    const float* gvfW = (const float*)d_in[1];
    const float* qW   = (const float*)d_in[2];
    const int*   gidx = (const int*)d_in[3];
    float* out = (float*)d_out;

    repack_kernel<<<(N_TOT + 255) / 256, 256>>>(gvfW, qW, gidx);

    cudaFuncSetAttribute(nibbler_main,
                         cudaFuncAttributeMaxDynamicSharedMemorySize, SMEM_BYTES);
    nibbler_main<<<2048 / ROWS, THREADS, SMEM_BYTES>>>(obs, out);
}